// round 15
// baseline (speedup 1.0000x reference)
#include <cuda_runtime.h>
#include <cuda_fp16.h>
#include <math.h>

#define N_NODES 100000
#define N_EDGES 1600000
#define IN_F 128
#define OUT_F 32
#define NEG_SLOPE 0.2f

#define ROWS_PB 128
#define K1_BLOCKS ((N_NODES + ROWS_PB - 1) / ROWS_PB)   // 782

#define SCAN_CHUNK 1024
#define SCAN_BLOCKS ((N_NODES + SCAN_CHUNK - 1) / SCAN_CHUNK)  // 98

// Scratch (device globals: no allocation allowed)
__device__ __half g_zh[(size_t)N_NODES * OUT_F];   // z in fp16 (6.4 MB)
__device__ float g_el[N_NODES];
__device__ float g_er[N_NODES];
__device__ int   g_cnt[N_NODES];      // per-node edge count
__device__ int   g_off[N_NODES];      // chunk-local excl offset; cursor during scatter
__device__ int   g_bsum[SCAN_BLOCKS]; // per-chunk totals
__device__ int   g_srce[N_EDGES];     // src ids sorted by dst

// ---------------------------------------------------------------------------
// helper: 98-entry exclusive prefix of g_bsum into smem pref[]
// ---------------------------------------------------------------------------
__device__ __forceinline__ void chunk_prefix(int* pref, int tid)
{
    int own = 0;
    if (tid < 128) {
        own = (tid < SCAN_BLOCKS) ? g_bsum[tid] : 0;
        pref[tid] = own;
    }
    __syncthreads();
    #pragma unroll
    for (int o = 1; o < 128; o <<= 1) {
        int v = 0;
        if (tid < 128 && tid >= o) v = pref[tid - o];
        __syncthreads();
        if (tid < 128) pref[tid] += v;
        __syncthreads();
    }
    if (tid < 128) pref[tid] -= own;     // inclusive -> exclusive
    __syncthreads();
}

// ---------------------------------------------------------------------------
// K1 (R6 core): z = h @ W^T (stored fp16), el/er row dots (fp32).
// 256 threads; tile 4 rows x 4 cols; h direct from global (broadcast
// LDG.128 per 8-lane group); W transposed in 16KB shared. Zeros g_cnt.
// ---------------------------------------------------------------------------
__global__ __launch_bounds__(256, 3) void k_gemm(
    const float* __restrict__ h, const float* __restrict__ W,
    const float* __restrict__ a)
{
    __shared__ float Wt[IN_F][OUT_F];       // 16 KB, Wt[k][j] = W[j][k]

    const int tid      = threadIdx.x;
    const int col0     = (tid & 7) * 4;
    const int row_grp  = tid >> 3;
    const int row_base = blockIdx.x * ROWS_PB + row_grp * 4;

    {
        int i = blockIdx.x * 256 + tid;
        if (i < N_NODES) g_cnt[i] = 0;
    }

    for (int i = tid; i < IN_F * OUT_F; i += 256) {
        int j = i >> 7;
        int k = i & 127;
        Wt[k][j] = W[i];
    }
    __syncthreads();

    int rows[4];
    #pragma unroll
    for (int i = 0; i < 4; i++) {
        int r = row_base + i;
        rows[i] = (r < N_NODES) ? r : (N_NODES - 1);
    }

    const float4* h4 = (const float4*)h;

    float4 acc[4];
    #pragma unroll
    for (int i = 0; i < 4; i++) acc[i] = make_float4(0.f, 0.f, 0.f, 0.f);

    #pragma unroll 4
    for (int k4 = 0; k4 < IN_F / 4; k4++) {
        float4 wv0 = *(const float4*)&Wt[k4 * 4 + 0][col0];
        float4 wv1 = *(const float4*)&Wt[k4 * 4 + 1][col0];
        float4 wv2 = *(const float4*)&Wt[k4 * 4 + 2][col0];
        float4 wv3 = *(const float4*)&Wt[k4 * 4 + 3][col0];

        #pragma unroll
        for (int i = 0; i < 4; i++) {
            float4 hv = h4[(size_t)rows[i] * (IN_F / 4) + k4];
            acc[i].x = fmaf(hv.x, wv0.x, acc[i].x);
            acc[i].y = fmaf(hv.x, wv0.y, acc[i].y);
            acc[i].z = fmaf(hv.x, wv0.z, acc[i].z);
            acc[i].w = fmaf(hv.x, wv0.w, acc[i].w);
            acc[i].x = fmaf(hv.y, wv1.x, acc[i].x);
            acc[i].y = fmaf(hv.y, wv1.y, acc[i].y);
            acc[i].z = fmaf(hv.y, wv1.z, acc[i].z);
            acc[i].w = fmaf(hv.y, wv1.w, acc[i].w);
            acc[i].x = fmaf(hv.z, wv2.x, acc[i].x);
            acc[i].y = fmaf(hv.z, wv2.y, acc[i].y);
            acc[i].z = fmaf(hv.z, wv2.z, acc[i].z);
            acc[i].w = fmaf(hv.z, wv2.w, acc[i].w);
            acc[i].x = fmaf(hv.w, wv3.x, acc[i].x);
            acc[i].y = fmaf(hv.w, wv3.y, acc[i].y);
            acc[i].z = fmaf(hv.w, wv3.z, acc[i].z);
            acc[i].w = fmaf(hv.w, wv3.w, acc[i].w);
        }
    }

    const float4 al4 = *(const float4*)&a[col0];
    const float4 ar4 = *(const float4*)&a[OUT_F + col0];

    #pragma unroll
    for (int i = 0; i < 4; i++) {
        int r = row_base + i;
        bool ok = (r < N_NODES);
        if (ok) {
            __half2 p0 = __floats2half2_rn(acc[i].x, acc[i].y);
            __half2 p1 = __floats2half2_rn(acc[i].z, acc[i].w);
            uint2 pk;
            pk.x = *(unsigned*)&p0;
            pk.y = *(unsigned*)&p1;
            ((uint2*)g_zh)[(size_t)r * (OUT_F / 4) + (col0 >> 2)] = pk;
        }

        float pel = acc[i].x * al4.x + acc[i].y * al4.y
                  + acc[i].z * al4.z + acc[i].w * al4.w;
        float per = acc[i].x * ar4.x + acc[i].y * ar4.y
                  + acc[i].z * ar4.z + acc[i].w * ar4.w;
        #pragma unroll
        for (int o = 4; o > 0; o >>= 1) {
            pel += __shfl_xor_sync(0xffffffffu, pel, o);
            per += __shfl_xor_sync(0xffffffffu, per, o);
        }
        if (ok && (tid & 7) == 0) {
            g_el[r] = pel;
            g_er[r] = per;
        }
    }
}

// ---------------------------------------------------------------------------
// A: histogram of dst, 4 edges/thread via int4
// ---------------------------------------------------------------------------
__global__ __launch_bounds__(256) void k_hist(const int* __restrict__ dst)
{
    int idx = blockIdx.x * 256 + threadIdx.x;
    if (idx >= N_EDGES / 4) return;
    int4 dv = ((const int4*)dst)[idx];
    atomicAdd(&g_cnt[dv.x], 1);
    atomicAdd(&g_cnt[dv.y], 1);
    atomicAdd(&g_cnt[dv.z], 1);
    atomicAdd(&g_cnt[dv.w], 1);
}

// ---------------------------------------------------------------------------
// B: per-chunk exclusive scan of g_cnt -> g_off (chunk-local), total -> g_bsum
// ---------------------------------------------------------------------------
__global__ __launch_bounds__(SCAN_CHUNK) void k_scan_local()
{
    __shared__ int wsum[32];
    int t = threadIdx.x;
    int i = blockIdx.x * SCAN_CHUNK + t;
    int c = (i < N_NODES) ? g_cnt[i] : 0;
    int lane = t & 31, wid = t >> 5;

    int incl = c;
    #pragma unroll
    for (int o = 1; o < 32; o <<= 1) {
        int v = __shfl_up_sync(0xffffffffu, incl, o);
        if (lane >= o) incl += v;
    }
    if (lane == 31) wsum[wid] = incl;
    __syncthreads();
    if (wid == 0) {
        int w = wsum[lane];
        int wincl = w;
        #pragma unroll
        for (int o = 1; o < 32; o <<= 1) {
            int v = __shfl_up_sync(0xffffffffu, wincl, o);
            if (lane >= o) wincl += v;
        }
        wsum[lane] = wincl - w;
        if (lane == 31) g_bsum[blockIdx.x] = wincl;
    }
    __syncthreads();
    if (i < N_NODES) g_off[i] = wsum[wid] + incl - c;   // chunk-local exclusive
}

// ---------------------------------------------------------------------------
// C: scatter src into dst-sorted order. Minimal L2 traffic per edge:
// one atomic RMW on g_off[d] (doubles as cursor) + one 4B write.
// No el/er reads (ex computed in aggregate).
// ---------------------------------------------------------------------------
__global__ __launch_bounds__(256) void k_scatter(
    const int* __restrict__ src, const int* __restrict__ dst)
{
    __shared__ int pref[128];
    const int tid = threadIdx.x;
    chunk_prefix(pref, tid);

    int idx = blockIdx.x * 256 + tid;
    if (idx >= N_EDGES / 4) return;
    int4 sv = ((const int4*)src)[idx];
    int4 dv = ((const int4*)dst)[idx];

    #pragma unroll
    for (int k = 0; k < 4; k++) {
        int sn = (k == 0) ? sv.x : (k == 1) ? sv.y : (k == 2) ? sv.z : sv.w;
        int d  = (k == 0) ? dv.x : (k == 1) ? dv.y : (k == 2) ? dv.z : dv.w;
        int pos = atomicAdd(&g_off[d], 1) + pref[d >> 10];
        g_srce[pos] = sn;
    }
}

// ---------------------------------------------------------------------------
// D: one warp per node: out[n] = (sum_e ex_e * z[src_e]) / (sum_e ex_e)
// ex computed here: er[node] is a broadcast, only el[sn] is a gather.
// 8 lanes per edge (uint2 = 4 halves each), 4 edges in parallel per warp.
// WARP-UNIFORM trip count (ceil(cnt/4)) so every __shfl_sync executes with
// all 32 lanes converged; invalid slots use sn=0 (safe gather) and ex=0.
// ---------------------------------------------------------------------------
__global__ __launch_bounds__(256) void k_aggregate(float* __restrict__ out)
{
    __shared__ int pref[128];
    const int tid = threadIdx.x;
    chunk_prefix(pref, tid);

    int node = blockIdx.x * 8 + (tid >> 5);   // 12500*8 == N_NODES, no tail
    int lane = tid & 31;
    int seg  = lane & 7;      // half4 chunk of z row / float4 chunk of out row
    int grp  = lane >> 3;     // 0..3: edge slot
    int base = lane & 24;     // group leader lane

    int cnt   = g_cnt[node];
    int start = g_off[node] - cnt + pref[node >> 10];
    float er_n = g_er[node];

    float4 acc = make_float4(0.f, 0.f, 0.f, 0.f);
    float exsum = 0.0f;

    int iters = (cnt + 3) >> 2;               // warp-uniform
    for (int it = 0; it < iters; it++) {
        int j = it * 4 + grp;
        bool valid = (j < cnt);
        int sn = 0;
        float ex = 0.0f;
        if (seg == 0 && valid) {
            sn = g_srce[start + j];
            float v = g_el[sn] + er_n;
            v = (v > 0.0f) ? v : NEG_SLOPE * v;
            ex = __expf(v);
        }
        sn = __shfl_sync(0xffffffffu, sn, base);
        ex = __shfl_sync(0xffffffffu, ex, base);

        uint2 zz = ((const uint2*)g_zh)[(size_t)sn * (OUT_F / 4) + seg];
        float2 f01 = __half22float2(*(__half2*)&zz.x);
        float2 f23 = __half22float2(*(__half2*)&zz.y);
        acc.x = fmaf(ex, f01.x, acc.x);
        acc.y = fmaf(ex, f01.y, acc.y);
        acc.z = fmaf(ex, f23.x, acc.z);
        acc.w = fmaf(ex, f23.y, acc.w);
        exsum += ex;
    }

    #pragma unroll
    for (int o = 8; o <= 16; o <<= 1) {
        acc.x += __shfl_xor_sync(0xffffffffu, acc.x, o);
        acc.y += __shfl_xor_sync(0xffffffffu, acc.y, o);
        acc.z += __shfl_xor_sync(0xffffffffu, acc.z, o);
        acc.w += __shfl_xor_sync(0xffffffffu, acc.w, o);
        exsum += __shfl_xor_sync(0xffffffffu, exsum, o);
    }

    float inv = 1.0f / fmaxf(exsum, 1e-16f);
    if (grp == 0) {
        float4 r = make_float4(acc.x * inv, acc.y * inv, acc.z * inv, acc.w * inv);
        ((float4*)(out + (size_t)node * OUT_F))[seg] = r;
    }
}

// ---------------------------------------------------------------------------
extern "C" void kernel_launch(void* const* d_in, const int* in_sizes, int n_in,
                              void* d_out, int out_size)
{
    const float* h   = (const float*)d_in[0];
    const float* W   = (const float*)d_in[1];
    const float* a   = (const float*)d_in[2];
    const int*   src = (const int*)d_in[3];
    const int*   dst = (const int*)d_in[4];
    float* out = (float*)d_out;

    (void)in_sizes; (void)n_in; (void)out_size;

    k_gemm<<<K1_BLOCKS, 256>>>(h, W, a);                       // 782 blocks
    k_hist<<<(N_EDGES / 4 + 255) / 256, 256>>>(dst);           // 1563
    k_scan_local<<<SCAN_BLOCKS, SCAN_CHUNK>>>();               // 98
    k_scatter<<<(N_EDGES / 4 + 255) / 256, 256>>>(src, dst);   // 1563
    k_aggregate<<<(N_NODES + 7) / 8, 256>>>(out);              // 12500
}

// round 16
// speedup vs baseline: 1.0639x; 1.0639x over previous
#include <cuda_runtime.h>
#include <cuda_fp16.h>
#include <math.h>

#define N_NODES 100000
#define N_EDGES 1600000
#define IN_F 128
#define OUT_F 32
#define NEG_SLOPE 0.2f

#define ROWS_PB 128
#define K1_BLOCKS ((N_NODES + ROWS_PB - 1) / ROWS_PB)   // 782

#define SCAN_CHUNK 1024
#define SCAN_BLOCKS ((N_NODES + SCAN_CHUNK - 1) / SCAN_CHUNK)  // 98

// Scratch (device globals: no allocation allowed)
__device__ __half g_zh[(size_t)N_NODES * OUT_F];   // z in fp16 (6.4 MB)
__device__ float g_el[N_NODES];
__device__ float g_er[N_NODES];
__device__ int   g_cnt[N_NODES];      // per-node edge count (hist result)
__device__ int   g_off[N_NODES];      // chunk-local exclusive offsets (stable)
__device__ int   g_bsum[SCAN_BLOCKS]; // per-chunk totals
__device__ int   g_rank[N_EDGES];     // per-edge rank within its dst node
__device__ int   g_srce[N_EDGES];     // src ids sorted by dst

// ---------------------------------------------------------------------------
// helper: 98-entry exclusive prefix of g_bsum into smem pref[]
// ---------------------------------------------------------------------------
__device__ __forceinline__ void chunk_prefix(int* pref, int tid)
{
    int own = 0;
    if (tid < 128) {
        own = (tid < SCAN_BLOCKS) ? g_bsum[tid] : 0;
        pref[tid] = own;
    }
    __syncthreads();
    #pragma unroll
    for (int o = 1; o < 128; o <<= 1) {
        int v = 0;
        if (tid < 128 && tid >= o) v = pref[tid - o];
        __syncthreads();
        if (tid < 128) pref[tid] += v;
        __syncthreads();
    }
    if (tid < 128) pref[tid] -= own;     // inclusive -> exclusive
    __syncthreads();
}

// ---------------------------------------------------------------------------
// K1 (R6 core): z = h @ W^T (stored fp16), el/er row dots (fp32).
// 256 threads; tile 4 rows x 4 cols; h direct from global (broadcast
// LDG.128 per 8-lane group); W transposed in 16KB shared. Zeros g_cnt.
// ---------------------------------------------------------------------------
__global__ __launch_bounds__(256, 3) void k_gemm(
    const float* __restrict__ h, const float* __restrict__ W,
    const float* __restrict__ a)
{
    __shared__ float Wt[IN_F][OUT_F];       // 16 KB, Wt[k][j] = W[j][k]

    const int tid      = threadIdx.x;
    const int col0     = (tid & 7) * 4;
    const int row_grp  = tid >> 3;
    const int row_base = blockIdx.x * ROWS_PB + row_grp * 4;

    {
        int i = blockIdx.x * 256 + tid;
        if (i < N_NODES) g_cnt[i] = 0;
    }

    for (int i = tid; i < IN_F * OUT_F; i += 256) {
        int j = i >> 7;
        int k = i & 127;
        Wt[k][j] = W[i];
    }
    __syncthreads();

    int rows[4];
    #pragma unroll
    for (int i = 0; i < 4; i++) {
        int r = row_base + i;
        rows[i] = (r < N_NODES) ? r : (N_NODES - 1);
    }

    const float4* h4 = (const float4*)h;

    float4 acc[4];
    #pragma unroll
    for (int i = 0; i < 4; i++) acc[i] = make_float4(0.f, 0.f, 0.f, 0.f);

    #pragma unroll 4
    for (int k4 = 0; k4 < IN_F / 4; k4++) {
        float4 wv0 = *(const float4*)&Wt[k4 * 4 + 0][col0];
        float4 wv1 = *(const float4*)&Wt[k4 * 4 + 1][col0];
        float4 wv2 = *(const float4*)&Wt[k4 * 4 + 2][col0];
        float4 wv3 = *(const float4*)&Wt[k4 * 4 + 3][col0];

        #pragma unroll
        for (int i = 0; i < 4; i++) {
            float4 hv = h4[(size_t)rows[i] * (IN_F / 4) + k4];
            acc[i].x = fmaf(hv.x, wv0.x, acc[i].x);
            acc[i].y = fmaf(hv.x, wv0.y, acc[i].y);
            acc[i].z = fmaf(hv.x, wv0.z, acc[i].z);
            acc[i].w = fmaf(hv.x, wv0.w, acc[i].w);
            acc[i].x = fmaf(hv.y, wv1.x, acc[i].x);
            acc[i].y = fmaf(hv.y, wv1.y, acc[i].y);
            acc[i].z = fmaf(hv.y, wv1.z, acc[i].z);
            acc[i].w = fmaf(hv.y, wv1.w, acc[i].w);
            acc[i].x = fmaf(hv.z, wv2.x, acc[i].x);
            acc[i].y = fmaf(hv.z, wv2.y, acc[i].y);
            acc[i].z = fmaf(hv.z, wv2.z, acc[i].z);
            acc[i].w = fmaf(hv.z, wv2.w, acc[i].w);
            acc[i].x = fmaf(hv.w, wv3.x, acc[i].x);
            acc[i].y = fmaf(hv.w, wv3.y, acc[i].y);
            acc[i].z = fmaf(hv.w, wv3.z, acc[i].z);
            acc[i].w = fmaf(hv.w, wv3.w, acc[i].w);
        }
    }

    const float4 al4 = *(const float4*)&a[col0];
    const float4 ar4 = *(const float4*)&a[OUT_F + col0];

    #pragma unroll
    for (int i = 0; i < 4; i++) {
        int r = row_base + i;
        bool ok = (r < N_NODES);
        if (ok) {
            __half2 p0 = __floats2half2_rn(acc[i].x, acc[i].y);
            __half2 p1 = __floats2half2_rn(acc[i].z, acc[i].w);
            uint2 pk;
            pk.x = *(unsigned*)&p0;
            pk.y = *(unsigned*)&p1;
            ((uint2*)g_zh)[(size_t)r * (OUT_F / 4) + (col0 >> 2)] = pk;
        }

        float pel = acc[i].x * al4.x + acc[i].y * al4.y
                  + acc[i].z * al4.z + acc[i].w * al4.w;
        float per = acc[i].x * ar4.x + acc[i].y * ar4.y
                  + acc[i].z * ar4.z + acc[i].w * ar4.w;
        #pragma unroll
        for (int o = 4; o > 0; o >>= 1) {
            pel += __shfl_xor_sync(0xffffffffu, pel, o);
            per += __shfl_xor_sync(0xffffffffu, per, o);
        }
        if (ok && (tid & 7) == 0) {
            g_el[r] = pel;
            g_er[r] = per;
        }
    }
}

// ---------------------------------------------------------------------------
// A: histogram of dst + per-edge rank. The atomic RMW lives here (it is the
// histogram anyway); rank stored coalesced so scatter needs NO atomics.
// ---------------------------------------------------------------------------
__global__ __launch_bounds__(256) void k_hist(const int* __restrict__ dst)
{
    int idx = blockIdx.x * 256 + threadIdx.x;
    if (idx >= N_EDGES / 4) return;
    int4 dv = ((const int4*)dst)[idx];
    int4 rv;
    rv.x = atomicAdd(&g_cnt[dv.x], 1);
    rv.y = atomicAdd(&g_cnt[dv.y], 1);
    rv.z = atomicAdd(&g_cnt[dv.z], 1);
    rv.w = atomicAdd(&g_cnt[dv.w], 1);
    ((int4*)g_rank)[idx] = rv;
}

// ---------------------------------------------------------------------------
// B: per-chunk exclusive scan of g_cnt -> g_off (chunk-local), total -> g_bsum
// ---------------------------------------------------------------------------
__global__ __launch_bounds__(SCAN_CHUNK) void k_scan_local()
{
    __shared__ int wsum[32];
    int t = threadIdx.x;
    int i = blockIdx.x * SCAN_CHUNK + t;
    int c = (i < N_NODES) ? g_cnt[i] : 0;
    int lane = t & 31, wid = t >> 5;

    int incl = c;
    #pragma unroll
    for (int o = 1; o < 32; o <<= 1) {
        int v = __shfl_up_sync(0xffffffffu, incl, o);
        if (lane >= o) incl += v;
    }
    if (lane == 31) wsum[wid] = incl;
    __syncthreads();
    if (wid == 0) {
        int w = wsum[lane];
        int wincl = w;
        #pragma unroll
        for (int o = 1; o < 32; o <<= 1) {
            int v = __shfl_up_sync(0xffffffffu, wincl, o);
            if (lane >= o) wincl += v;
        }
        wsum[lane] = wincl - w;
        if (lane == 31) g_bsum[blockIdx.x] = wincl;
    }
    __syncthreads();
    if (i < N_NODES) g_off[i] = wsum[wid] + incl - c;   // chunk-local exclusive
}

// ---------------------------------------------------------------------------
// C: ATOMIC-FREE scatter: pos = off[d] + pref + rank[e]. One random 4B read
// (off gather) + one scattered 4B write per edge, all independent -> high MLP.
// ---------------------------------------------------------------------------
__global__ __launch_bounds__(256) void k_scatter(
    const int* __restrict__ src, const int* __restrict__ dst)
{
    __shared__ int pref[128];
    const int tid = threadIdx.x;
    chunk_prefix(pref, tid);

    int idx = blockIdx.x * 256 + tid;
    if (idx >= N_EDGES / 4) return;
    int4 sv = ((const int4*)src)[idx];
    int4 dv = ((const int4*)dst)[idx];
    int4 rv = ((const int4*)g_rank)[idx];

    g_srce[g_off[dv.x] + pref[dv.x >> 10] + rv.x] = sv.x;
    g_srce[g_off[dv.y] + pref[dv.y >> 10] + rv.y] = sv.y;
    g_srce[g_off[dv.z] + pref[dv.z >> 10] + rv.z] = sv.z;
    g_srce[g_off[dv.w] + pref[dv.w >> 10] + rv.w] = sv.w;
}

// ---------------------------------------------------------------------------
// D: one warp per node. Per 32-edge chunk:
//   phase 1: lane l loads srce[start+l] COALESCED, gathers el (32 parallel
//            loads), computes ex -> per-lane registers. exsum accumulated.
//   phase 2: inner loop only shfl-broadcasts (sn, ex); the z gather is the
//            sole load, iteration-independent -> pipelined.
// All control flow warp-uniform; shfls fully converged.
// ---------------------------------------------------------------------------
__global__ __launch_bounds__(256) void k_aggregate(float* __restrict__ out)
{
    __shared__ int pref[128];
    const int tid = threadIdx.x;
    chunk_prefix(pref, tid);

    int node = blockIdx.x * 8 + (tid >> 5);   // 12500*8 == N_NODES, no tail
    int lane = tid & 31;
    int seg  = lane & 7;      // half4 chunk of z row / float4 chunk of out row
    int grp  = lane >> 3;     // 0..3: edge slot within a 4-edge batch

    int cnt   = g_cnt[node];
    int start = g_off[node] + pref[node >> 10];
    float er_n = g_er[node];

    float4 acc = make_float4(0.f, 0.f, 0.f, 0.f);
    float exsum = 0.0f;

    for (int b = 0; b < cnt; b += 32) {
        int nb = cnt - b;                      // warp-uniform
        if (nb > 32) nb = 32;

        // phase 1: coalesced srce + parallel el gathers
        bool v = (lane < nb);
        int sn = 0;
        float ex = 0.0f;
        if (v) {
            sn = g_srce[start + b + lane];
            float e = g_el[sn] + er_n;
            e = (e > 0.0f) ? e : NEG_SLOPE * e;
            ex = __expf(e);
        }
        exsum += ex;

        // phase 2: z accumulation, 4 edges x 8 segs per iteration
        int iters = (nb + 3) >> 2;             // warp-uniform
        #pragma unroll 4
        for (int it = 0; it < iters; it++) {
            int sl = it * 4 + grp;             // source lane (0..31)
            int   snb = __shfl_sync(0xffffffffu, sn, sl);
            float exb = __shfl_sync(0xffffffffu, ex, sl);  // 0 for invalid
            uint2 zz = ((const uint2*)g_zh)[(size_t)snb * (OUT_F / 4) + seg];
            float2 f01 = __half22float2(*(__half2*)&zz.x);
            float2 f23 = __half22float2(*(__half2*)&zz.y);
            acc.x = fmaf(exb, f01.x, acc.x);
            acc.y = fmaf(exb, f01.y, acc.y);
            acc.z = fmaf(exb, f23.x, acc.z);
            acc.w = fmaf(exb, f23.y, acc.w);
        }
    }

    // exsum: full-warp reduce; acc: reduce across the 4 groups (bits 3,4)
    #pragma unroll
    for (int o = 1; o < 32; o <<= 1)
        exsum += __shfl_xor_sync(0xffffffffu, exsum, o);
    #pragma unroll
    for (int o = 8; o <= 16; o <<= 1) {
        acc.x += __shfl_xor_sync(0xffffffffu, acc.x, o);
        acc.y += __shfl_xor_sync(0xffffffffu, acc.y, o);
        acc.z += __shfl_xor_sync(0xffffffffu, acc.z, o);
        acc.w += __shfl_xor_sync(0xffffffffu, acc.w, o);
    }

    float inv = 1.0f / fmaxf(exsum, 1e-16f);
    if (grp == 0) {
        float4 r = make_float4(acc.x * inv, acc.y * inv, acc.z * inv, acc.w * inv);
        ((float4*)(out + (size_t)node * OUT_F))[seg] = r;
    }
}

// ---------------------------------------------------------------------------
extern "C" void kernel_launch(void* const* d_in, const int* in_sizes, int n_in,
                              void* d_out, int out_size)
{
    const float* h   = (const float*)d_in[0];
    const float* W   = (const float*)d_in[1];
    const float* a   = (const float*)d_in[2];
    const int*   src = (const int*)d_in[3];
    const int*   dst = (const int*)d_in[4];
    float* out = (float*)d_out;

    (void)in_sizes; (void)n_in; (void)out_size;

    k_gemm<<<K1_BLOCKS, 256>>>(h, W, a);                       // 782 blocks
    k_hist<<<(N_EDGES / 4 + 255) / 256, 256>>>(dst);           // 1563
    k_scan_local<<<SCAN_BLOCKS, SCAN_CHUNK>>>();               // 98
    k_scatter<<<(N_EDGES / 4 + 255) / 256, 256>>>(src, dst);   // 1563
    k_aggregate<<<(N_NODES + 7) / 8, 256>>>(out);              // 12500
}